// round 12
// baseline (speedup 1.0000x reference)
#include <cuda_runtime.h>

// ---------------------------------------------------------------------------
// DifferentiableRenderer: Gaussian splat weighted-average render.
// out[b,c,y,x] = sum_n w_n*color_n / (sum_n w_n + 1e-8)
// w_n = opacity_n * exp(-0.5*((x-u_n)^2+(y-v_n)^2)/var_n)
//
// R12: merge is partial-traffic bound (R11 evidence: 4MB @ 815GB/s = 5.15us
//      regardless of block count). SPLIT 8->4 halves partial bytes; merge
//      becomes a flat 1-pixel/thread kernel with 4 independent ldcg loads
//      (fixed slice order -> deterministic). Render path unchanged:
//      fused prep + conservative tile cull + stable ballot compaction +
//      per-pixel eval. Cut at w < 2^-60: abs err <= ~7e-7 << 1e-3.
// ---------------------------------------------------------------------------

#define HH 128
#define WW 128
#define HWP (HH * WW)
#define FXC 150.0f
#define FYC 150.0f
#define CXC 64.0f
#define CYC 64.0f
#define EPSC 1e-8f

#define TILE    16
#define TX_N    (WW / TILE)          // 8
#define TY_N    (HH / TILE)          // 8
#define TILES   (TX_N * TY_N)        // 64
#define SPLIT   4                    // gaussian slices per tile
#define TPB     256                  // threads per render block (1 px each)
#define CHUNK   256                  // gaussians prepped+tested per pass
#define EMIN    (-60.0f)             // log2 weight cutoff

#define MAXB    4

// per (b, tile, split, pixel) partial sums {den, r, g, b}
__device__ float4 g_part[MAXB * TILES * SPLIT * TPB];

__device__ __forceinline__ float ex2f(float x) {
    float y;
    asm("ex2.approx.ftz.f32 %0, %1;" : "=f"(y) : "f"(x));
    return y;
}
__device__ __forceinline__ float lg2f(float x) {
    float y;
    asm("lg2.approx.ftz.f32 %0, %1;" : "=f"(y) : "f"(x));
    return y;
}

// ---------------------------------------------------------------------------
// Render: blockIdx.x = ((b*TILES + tile)*SPLIT + s). 256 threads = one 16x16
// pixel tile. Scan this block's gaussian slice in chunks:
//   prep (raw inputs -> u,v,a,bop) -> tile cull -> stable compaction -> eval.
// ---------------------------------------------------------------------------
__global__ void __launch_bounds__(TPB)
render_tiles(const float* __restrict__ pos,
             const float* __restrict__ col,
             const float* __restrict__ opac,
             const float* __restrict__ scal,
             const float* __restrict__ qv,
             const float* __restrict__ tv,
             int N) {
    __shared__ float4 sga[CHUNK];      // u, v, a, bop
    __shared__ float4 sgb[CHUNK];      // cr, cg, cb, -
    __shared__ int s_wbase[TPB / 32];
    __shared__ int s_wcnt[TPB / 32];
    __shared__ int s_total;

    const int tid  = threadIdx.x;
    const int bid  = blockIdx.x;
    const int s    = bid & (SPLIT - 1);
    const int tile = (bid / SPLIT) & (TILES - 1);
    const int b    = bid / (SPLIT * TILES);

    const int tx = tile & (TX_N - 1);
    const int ty = tile / TX_N;
    const float pxf = (float)(tx * TILE + (tid & (TILE - 1)));
    const float pyf = (float)(ty * TILE + (tid / TILE));
    const float tcx = (float)(tx * TILE) + 7.5f;   // tile center
    const float tcy = (float)(ty * TILE) + 7.5f;

    // --- per-batch camera, hoisted (broadcast loads, L1 hits) ---
    float qw = qv[b * 4 + 0], qx = qv[b * 4 + 1];
    float qy = qv[b * 4 + 2], qz = qv[b * 4 + 3];
    {
        float inv = rsqrtf(qw * qw + qx * qx + qy * qy + qz * qz);
        qw *= inv; qx *= inv; qy *= inv; qz *= inv;
    }
    const float R00 = 1.0f - 2.0f * (qy * qy + qz * qz);
    const float R01 = 2.0f * (qx * qy - qz * qw);
    const float R02 = 2.0f * (qx * qz + qy * qw);
    const float R10 = 2.0f * (qx * qy + qz * qw);
    const float R11 = 1.0f - 2.0f * (qx * qx + qz * qz);
    const float R12 = 2.0f * (qy * qz - qx * qw);
    const float R20 = 2.0f * (qx * qz - qy * qw);
    const float R21 = 2.0f * (qy * qz + qx * qw);
    const float R22 = 1.0f - 2.0f * (qx * qx + qy * qy);
    const float t0 = tv[b * 3 + 0], t1 = tv[b * 3 + 1], t2 = tv[b * 3 + 2];

    const int lo = (s * N) / SPLIT;
    const int hi = ((s + 1) * N) / SPLIT;

    const int wid  = tid >> 5;
    const int lane = tid & 31;
    const unsigned lanemask_lt = (1u << lane) - 1u;

    float den = 0.f, ar = 0.f, ag = 0.f, ab = 0.f;

    for (int cb = lo; cb < hi; cb += CHUNK) {
        // --- prep + cull one gaussian per thread ---
        const int j = cb + tid;                    // gaussian index
        bool keep = false;
        float4 ga;
        if (j < hi) {
            const float px = pos[j * 3 + 0];
            const float py = pos[j * 3 + 1];
            const float pz = pos[j * 3 + 2];
            const float cxm = R00 * px + R01 * py + R02 * pz + t0;
            const float cym = R10 * px + R11 * py + R12 * pz + t1;
            const float czm = R20 * px + R21 * py + R22 * pz + t2;
            const float invz = __fdividef(1.0f, czm);
            const float u = cxm * invz * FXC + CXC;
            const float v = cym * invz * FYC + CYC;
            const float sc = scal[j];
            // a = -0.5 * log2(e) / var
            const float a = __fdividef(-0.72134752044448170f, sc * sc);
            const float bop = lg2f(opac[j]);       // opac=0 -> -inf -> culled
            ga = make_float4(u, v, a, bop);

            float dx = fmaxf(fabsf(u - tcx) - 7.5f, 0.0f);
            float dy = fmaxf(fabsf(v - tcy) - 7.5f, 0.0f);
            float mind2 = dx * dx + dy * dy;
            float emax  = fmaf(a, mind2, bop);     // a*mind2 + bop (a<0)
            keep = (emax >= EMIN);
        }

        // --- stable compaction (gaussian-index order preserved) ---
        const unsigned mask = __ballot_sync(0xffffffffu, keep);
        if (lane == 0) s_wcnt[wid] = __popc(mask);
        __syncthreads();
        if (tid == 0) {
            int acc = 0;
            #pragma unroll
            for (int w = 0; w < TPB / 32; w++) { s_wbase[w] = acc; acc += s_wcnt[w]; }
            s_total = acc;
        }
        __syncthreads();
        if (keep) {
            const int posn = s_wbase[wid] + __popc(mask & lanemask_lt);
            sga[posn] = ga;
            sgb[posn] = make_float4(col[j * 3 + 0], col[j * 3 + 1],
                                    col[j * 3 + 2], 0.0f);
        }
        __syncthreads();

        // --- evaluate survivors against this thread's pixel ---
        const int cnt = s_total;
        #pragma unroll 2
        for (int t = 0; t < cnt; t++) {
            const float4 A  = sga[t];              // u, v, a, bop (broadcast)
            const float4 Cc = sgb[t];
            const float dv = pyf - A.y;
            const float c2 = fmaf(A.z * dv, dv, A.w);
            const float du = pxf - A.x;
            const float e  = fmaf(A.z * du, du, c2);
            const float w  = ex2f(e);
            den += w;
            ar = fmaf(w, Cc.x, ar);
            ag = fmaf(w, Cc.y, ag);
            ab = fmaf(w, Cc.z, ab);
        }
        __syncthreads();
    }

    // publish partial to L2 (consumed once by merge kernel)
    __stcg(&g_part[bid * TPB + tid], make_float4(den, ar, ag, ab));
}

// ---------------------------------------------------------------------------
// Merge: grid = B*TILES*2 blocks x 128 threads; one pixel per thread.
// 4 independent ldcg loads (MLP=4), fixed slice order (deterministic),
// divide, store 3 planes. No smem, no syncs.
// ---------------------------------------------------------------------------
__global__ void __launch_bounds__(128)
merge_kernel(float* __restrict__ out) {
    const int tid  = threadIdx.x;
    const int half = blockIdx.x & 1;         // tile half
    const int m    = blockIdx.x >> 1;        // b*TILES + tile
    const int tile = m & (TILES - 1);
    const int b    = m / TILES;
    const int pix  = half * 128 + tid;       // pixel within tile

    const float4 p0 = __ldcg(&g_part[(m * SPLIT + 0) * TPB + pix]);
    const float4 p1 = __ldcg(&g_part[(m * SPLIT + 1) * TPB + pix]);
    const float4 p2 = __ldcg(&g_part[(m * SPLIT + 2) * TPB + pix]);
    const float4 p3 = __ldcg(&g_part[(m * SPLIT + 3) * TPB + pix]);

    // fixed order -> deterministic
    float4 acc;
    acc.x = ((p0.x + p1.x) + (p2.x + p3.x));
    acc.y = ((p0.y + p1.y) + (p2.y + p3.y));
    acc.z = ((p0.z + p1.z) + (p2.z + p3.z));
    acc.w = ((p0.w + p1.w) + (p2.w + p3.w));

    const float invd = __fdividef(1.0f, acc.x + EPSC);

    const int tx = tile & (TX_N - 1);
    const int ty = tile / TX_N;
    const int px = tx * TILE + (pix & (TILE - 1));
    const int py = ty * TILE + (pix / TILE);
    float* ob = out + (size_t)b * 3 * HWP + py * WW + px;
    ob[0]       = acc.y * invd;   // R plane
    ob[HWP]     = acc.z * invd;   // G plane
    ob[2 * HWP] = acc.w * invd;   // B plane
}

// ---------------------------------------------------------------------------
extern "C" void kernel_launch(void* const* d_in, const int* in_sizes, int n_in,
                              void* d_out, int out_size) {
    const float* positions = (const float*)d_in[0];
    const float* colors    = (const float*)d_in[1];
    const float* opacities = (const float*)d_in[2];
    const float* scales    = (const float*)d_in[3];
    const float* qvec      = (const float*)d_in[4];
    const float* tvec      = (const float*)d_in[5];
    float* out = (float*)d_out;

    const int N = in_sizes[0] / 3;
    const int B = in_sizes[4] / 4;

    render_tiles<<<B * TILES * SPLIT, TPB>>>(positions, colors, opacities,
                                             scales, qvec, tvec, N);
    merge_kernel<<<B * TILES * 2, 128>>>(out);
}

// round 13
// speedup vs baseline: 1.0280x; 1.0280x over previous
#include <cuda_runtime.h>

// ---------------------------------------------------------------------------
// DifferentiableRenderer: Gaussian splat weighted-average render.
// out[b,c,y,x] = sum_n w_n*color_n / (sum_n w_n + 1e-8)
// w_n = opacity_n * exp(-0.5*((x-u_n)^2+(y-v_n)^2)/var_n)
//
// R13: single kernel. Evidence: every small kernel in this harness costs
//   ~4.5us regardless of work (prep 5.7, merges 4.9/5.2/4.5 across shapes),
//   so the merge LAUNCH is the cost, not the merge. Fuse it back, but unlike
//   R10: no __threadfence (MEMBAR.GPU drain) -- one atom.acq_rel.gpu on a
//   per-tile counter publishes stcg partials (L2) to the last-arriving
//   block, which merges 4 partials in FIXED slice order (deterministic),
//   divides, stores, resets the counter for graph replay. SPLIT=4 keeps
//   straggler depth low. Render body unchanged from R12 (fused prep +
//   conservative tile cull + stable ballot compaction + per-pixel eval).
//   Cut at w < 2^-60: per-pixel abs error <= ~7e-7 << 1e-3 budget.
// ---------------------------------------------------------------------------

#define HH 128
#define WW 128
#define HWP (HH * WW)
#define FXC 150.0f
#define FYC 150.0f
#define CXC 64.0f
#define CYC 64.0f
#define EPSC 1e-8f

#define TILE    16
#define TX_N    (WW / TILE)          // 8
#define TY_N    (HH / TILE)          // 8
#define TILES   (TX_N * TY_N)        // 64
#define SPLIT   4                    // gaussian slices per tile
#define TPB     256                  // threads per render block (1 px each)
#define CHUNK   256                  // gaussians prepped+tested per pass
#define EMIN    (-60.0f)             // log2 weight cutoff

#define MAXB    4

// per (b, tile, split, pixel) partial sums {den, r, g, b} -- L2 resident
__device__ float4 g_part[MAXB * TILES * SPLIT * TPB];
// per (b, tile) arrival counters (zero-init; reset by merging block)
__device__ int g_cnt[MAXB * TILES];

__device__ __forceinline__ float ex2f(float x) {
    float y;
    asm("ex2.approx.ftz.f32 %0, %1;" : "=f"(y) : "f"(x));
    return y;
}
__device__ __forceinline__ float lg2f(float x) {
    float y;
    asm("lg2.approx.ftz.f32 %0, %1;" : "=f"(y) : "f"(x));
    return y;
}
// fetch-add with acq_rel at gpu scope: releases our prior stores, acquires
// peers' released stores. No MEMBAR drain.
__device__ __forceinline__ int atom_add_acqrel(int* p, int v) {
    int old;
    asm volatile("atom.add.acq_rel.gpu.global.s32 %0, [%1], %2;"
                 : "=r"(old) : "l"(p), "r"(v) : "memory");
    return old;
}

// ---------------------------------------------------------------------------
// blockIdx.x = ((b*TILES + tile)*SPLIT + s). 256 threads = one 16x16 tile.
// ---------------------------------------------------------------------------
__global__ void __launch_bounds__(TPB)
render_tiles(float* __restrict__ out,
             const float* __restrict__ pos,
             const float* __restrict__ col,
             const float* __restrict__ opac,
             const float* __restrict__ scal,
             const float* __restrict__ qv,
             const float* __restrict__ tv,
             int N) {
    __shared__ float4 sga[CHUNK];      // u, v, a, bop
    __shared__ float4 sgb[CHUNK];      // cr, cg, cb, -
    __shared__ int s_wbase[TPB / 32];
    __shared__ int s_wcnt[TPB / 32];
    __shared__ int s_total;
    __shared__ int s_arrival;

    const int tid  = threadIdx.x;
    const int bid  = blockIdx.x;
    const int s    = bid & (SPLIT - 1);
    const int tile = (bid / SPLIT) & (TILES - 1);
    const int b    = bid / (SPLIT * TILES);
    const int m    = b * TILES + tile;            // tile slot

    const int tx = tile & (TX_N - 1);
    const int ty = tile / TX_N;
    const float pxf = (float)(tx * TILE + (tid & (TILE - 1)));
    const float pyf = (float)(ty * TILE + (tid / TILE));
    const float tcx = (float)(tx * TILE) + 7.5f;   // tile center
    const float tcy = (float)(ty * TILE) + 7.5f;

    // --- per-batch camera, hoisted (broadcast loads, L1 hits) ---
    float qw = qv[b * 4 + 0], qx = qv[b * 4 + 1];
    float qy = qv[b * 4 + 2], qz = qv[b * 4 + 3];
    {
        float inv = rsqrtf(qw * qw + qx * qx + qy * qy + qz * qz);
        qw *= inv; qx *= inv; qy *= inv; qz *= inv;
    }
    const float R00 = 1.0f - 2.0f * (qy * qy + qz * qz);
    const float R01 = 2.0f * (qx * qy - qz * qw);
    const float R02 = 2.0f * (qx * qz + qy * qw);
    const float R10 = 2.0f * (qx * qy + qz * qw);
    const float R11 = 1.0f - 2.0f * (qx * qx + qz * qz);
    const float R12 = 2.0f * (qy * qz - qx * qw);
    const float R20 = 2.0f * (qx * qz - qy * qw);
    const float R21 = 2.0f * (qy * qz + qx * qw);
    const float R22 = 1.0f - 2.0f * (qx * qx + qy * qy);
    const float t0 = tv[b * 3 + 0], t1 = tv[b * 3 + 1], t2 = tv[b * 3 + 2];

    const int lo = (s * N) / SPLIT;
    const int hi = ((s + 1) * N) / SPLIT;

    const int wid  = tid >> 5;
    const int lane = tid & 31;
    const unsigned lanemask_lt = (1u << lane) - 1u;

    float den = 0.f, ar = 0.f, ag = 0.f, ab = 0.f;

    for (int cb = lo; cb < hi; cb += CHUNK) {
        // --- prep + cull one gaussian per thread ---
        const int j = cb + tid;                    // gaussian index
        bool keep = false;
        float4 ga;
        if (j < hi) {
            const float px = pos[j * 3 + 0];
            const float py = pos[j * 3 + 1];
            const float pz = pos[j * 3 + 2];
            const float cxm = R00 * px + R01 * py + R02 * pz + t0;
            const float cym = R10 * px + R11 * py + R12 * pz + t1;
            const float czm = R20 * px + R21 * py + R22 * pz + t2;
            const float invz = __fdividef(1.0f, czm);
            const float u = cxm * invz * FXC + CXC;
            const float v = cym * invz * FYC + CYC;
            const float sc = scal[j];
            // a = -0.5 * log2(e) / var
            const float a = __fdividef(-0.72134752044448170f, sc * sc);
            const float bop = lg2f(opac[j]);       // opac=0 -> -inf -> culled
            ga = make_float4(u, v, a, bop);

            float dx = fmaxf(fabsf(u - tcx) - 7.5f, 0.0f);
            float dy = fmaxf(fabsf(v - tcy) - 7.5f, 0.0f);
            float mind2 = dx * dx + dy * dy;
            float emax  = fmaf(a, mind2, bop);     // a*mind2 + bop (a<0)
            keep = (emax >= EMIN);
        }

        // --- stable compaction (gaussian-index order preserved) ---
        const unsigned mask = __ballot_sync(0xffffffffu, keep);
        if (lane == 0) s_wcnt[wid] = __popc(mask);
        __syncthreads();
        if (tid == 0) {
            int acc = 0;
            #pragma unroll
            for (int w = 0; w < TPB / 32; w++) { s_wbase[w] = acc; acc += s_wcnt[w]; }
            s_total = acc;
        }
        __syncthreads();
        if (keep) {
            const int posn = s_wbase[wid] + __popc(mask & lanemask_lt);
            sga[posn] = ga;
            sgb[posn] = make_float4(col[j * 3 + 0], col[j * 3 + 1],
                                    col[j * 3 + 2], 0.0f);
        }
        __syncthreads();

        // --- evaluate survivors against this thread's pixel ---
        const int cnt = s_total;
        #pragma unroll 2
        for (int t = 0; t < cnt; t++) {
            const float4 A  = sga[t];              // u, v, a, bop (broadcast)
            const float4 Cc = sgb[t];
            const float dv = pyf - A.y;
            const float c2 = fmaf(A.z * dv, dv, A.w);
            const float du = pxf - A.x;
            const float e  = fmaf(A.z * du, du, c2);
            const float w  = ex2f(e);
            den += w;
            ar = fmaf(w, Cc.x, ar);
            ag = fmaf(w, Cc.y, ag);
            ab = fmaf(w, Cc.z, ab);
        }
        __syncthreads();
    }

    // --- publish this slice's partial to L2 ---
    __stcg(&g_part[bid * TPB + tid], make_float4(den, ar, ag, ab));
    __syncthreads();   // intra-block HB: all stores precede tid0's release

    // --- last-arriving block of this tile merges ---
    if (tid == 0) s_arrival = atom_add_acqrel(&g_cnt[m], 1);
    __syncthreads();   // acquire by tid0 + barrier -> HB for all readers

    if (s_arrival == SPLIT - 1) {
        // all 4 partials for tile m visible in L2 (release/acquire chain)
        const float4 p0 = __ldcg(&g_part[(m * SPLIT + 0) * TPB + tid]);
        const float4 p1 = __ldcg(&g_part[(m * SPLIT + 1) * TPB + tid]);
        const float4 p2 = __ldcg(&g_part[(m * SPLIT + 2) * TPB + tid]);
        const float4 p3 = __ldcg(&g_part[(m * SPLIT + 3) * TPB + tid]);

        // fixed slice order -> deterministic regardless of merger identity
        float4 acc;
        acc.x = (p0.x + p1.x) + (p2.x + p3.x);
        acc.y = (p0.y + p1.y) + (p2.y + p3.y);
        acc.z = (p0.z + p1.z) + (p2.z + p3.z);
        acc.w = (p0.w + p1.w) + (p2.w + p3.w);

        const float invd = __fdividef(1.0f, acc.x + EPSC);

        const int px = tx * TILE + (tid & (TILE - 1));
        const int py = ty * TILE + (tid / TILE);
        float* ob = out + (size_t)b * 3 * HWP + py * WW + px;
        ob[0]       = acc.y * invd;   // R plane
        ob[HWP]     = acc.z * invd;   // G plane
        ob[2 * HWP] = acc.w * invd;   // B plane

        if (tid == 0) g_cnt[m] = 0;   // reset for next launch / graph replay
    }
}

// ---------------------------------------------------------------------------
extern "C" void kernel_launch(void* const* d_in, const int* in_sizes, int n_in,
                              void* d_out, int out_size) {
    const float* positions = (const float*)d_in[0];
    const float* colors    = (const float*)d_in[1];
    const float* opacities = (const float*)d_in[2];
    const float* scales    = (const float*)d_in[3];
    const float* qvec      = (const float*)d_in[4];
    const float* tvec      = (const float*)d_in[5];
    float* out = (float*)d_out;

    const int N = in_sizes[0] / 3;
    const int B = in_sizes[4] / 4;

    render_tiles<<<B * TILES * SPLIT, TPB>>>(out, positions, colors, opacities,
                                             scales, qvec, tvec, N);
}